// round 9
// baseline (speedup 1.0000x reference)
#include <cuda_runtime.h>
#include <cuda_bf16.h>
#include <cstdint>

#define NROWS 32768
#define DIM   256
#define NC    8192
#define HM    1e-4f             // score-space margin (= 2e-4 in dist space)
#define CAP   32

#define PITCHA 264              // bf16 elems/row for A smem
#define PITCHB 136              // bf16 elems/row for B smem (128 dims + pad)
#define BBUF   34816            // 128*136*2 bytes per B stage
// smem byte offsets
#define SM_A    0
#define SM_B    67584
#define SM_CAND (SM_B + 3*BBUF)            // 172032
#define SM_RMAX (SM_CAND + 128*CAP*4)      // 188416
#define SM_CNT  (SM_RMAX + 512)            // 188928
#define SMEM_TOTAL (SM_CNT + 512)          // 189440

#define NTHR 512

// ---------------- scratch ----------------------------------------------------
__device__ float g_sumz[NROWS];
__device__ float g_cnorm[NC];
__device__ float g_count[NC];
__device__ float g_wsum[NC * DIM];
__device__ float g_loss;
__device__ float g_n;
__device__ __nv_bfloat16 g_zb[NROWS * DIM];
__device__ __nv_bfloat16 g_cb[NC * DIM];

// ---------------- helpers -----------------------------------------------------
__device__ __forceinline__ uint32_t smem_u32(const void* p) {
    uint32_t a;
    asm("{ .reg .u64 t; cvta.to.shared.u64 t, %1; cvt.u32.u64 %0, t; }" : "=r"(a) : "l"(p));
    return a;
}
__device__ __forceinline__ void ldsm4(uint32_t& r0, uint32_t& r1, uint32_t& r2, uint32_t& r3, uint32_t addr) {
    asm volatile("ldmatrix.sync.aligned.m8n8.x4.shared.b16 {%0,%1,%2,%3}, [%4];"
                 : "=r"(r0), "=r"(r1), "=r"(r2), "=r"(r3) : "r"(addr));
}
__device__ __forceinline__ void mma16816(float* c, uint32_t a0, uint32_t a1, uint32_t a2, uint32_t a3,
                                         uint32_t b0, uint32_t b1) {
    asm volatile("mma.sync.aligned.m16n8k16.row.col.f32.bf16.bf16.f32 "
                 "{%0,%1,%2,%3}, {%4,%5,%6,%7}, {%8,%9}, {%0,%1,%2,%3};"
                 : "+f"(c[0]), "+f"(c[1]), "+f"(c[2]), "+f"(c[3])
                 : "r"(a0), "r"(a1), "r"(a2), "r"(a3), "r"(b0), "r"(b1));
}
__device__ __forceinline__ void cpasync16(uint32_t dst, const void* src) {
    asm volatile("cp.async.cg.shared.global [%0], [%1], 16;" :: "r"(dst), "l"(src));
}
// order-preserving float<->uint map (unsigned compare == float compare)
__device__ __forceinline__ uint32_t fmap(float f) {
    uint32_t b = __float_as_uint(f);
    return b ^ (uint32_t)(((int32_t)b >> 31) | 0x80000000);
}
__device__ __forceinline__ float funmap(uint32_t u) {
    uint32_t b = u ^ ((u >> 31) ? 0x80000000u : 0xFFFFFFFFu);
    return __uint_as_float(b);
}

// ---------------- zero scratch ------------------------------------------------
__global__ void k_zero() {
    int i = blockIdx.x * blockDim.x + threadIdx.x;
    int stride = gridDim.x * blockDim.x;
    for (int j = i; j < NC * DIM; j += stride) g_wsum[j] = 0.0f;
    if (i < NC) g_count[i] = 0.0f;
    if (i == 0) { g_loss = 0.0f; g_n = 0.0f; }
}

// ---------------- prep: row norms + bf16 round --------------------------------
__global__ void k_prep(const float* __restrict__ x, __nv_bfloat16* __restrict__ ob,
                       float* __restrict__ norm, int rows) {
    int w = (blockIdx.x * blockDim.x + threadIdx.x) >> 5;
    int lane = threadIdx.x & 31;
    if (w >= rows) return;
    const float* row = x + (size_t)w * DIM;
    float s = 0.0f;
#pragma unroll
    for (int m = 0; m < 8; m++) { float v = row[lane + 32*m]; s = __fadd_rn(s, __fmul_rn(v, v)); }
#pragma unroll
    for (int o = 16; o > 0; o >>= 1) s = __fadd_rn(s, __shfl_down_sync(0xffffffffu, s, o));
    if (lane == 0) norm[w] = s;

    __align__(16) __nv_bfloat16 b0[8];
#pragma unroll
    for (int q = 0; q < 8; q++) b0[q] = __float2bfloat16_rn(row[lane*8 + q]);
    *reinterpret_cast<uint4*>(ob + (size_t)w*DIM + lane*8) = *reinterpret_cast<uint4*>(b0);
}

// ---------------- fused: HMMA GEMM + candidates + exact argmin + scatter -------
// grid = 256 CTAs (one per 128-row chunk); loops all 64 code chunks. 512 thr.
__global__ void __launch_bounds__(NTHR, 1) k_mma(
    const __nv_bfloat16* __restrict__ zb, const __nv_bfloat16* __restrict__ cb,
    const float* __restrict__ zf, const float* __restrict__ cbw,
    const float* __restrict__ sumz, const float* __restrict__ cnorm,
    float* __restrict__ idxf_out, float* __restrict__ zq_out,
    float* __restrict__ wsum, float* __restrict__ cnt, float* __restrict__ lossacc)
{
    extern __shared__ char smem[];
    __nv_bfloat16* As = reinterpret_cast<__nv_bfloat16*>(smem + SM_A);
    int*       scand = reinterpret_cast<int*>(smem + SM_CAND);
    uint32_t*  srmax = reinterpret_cast<uint32_t*>(smem + SM_RMAX);
    int*       scnt  = reinterpret_cast<int*>(smem + SM_CNT);

    const int tid = threadIdx.x;
    const int row0 = blockIdx.x * 128;
    const uint32_t sbA = smem_u32(smem + SM_A);
    const uint32_t sbB = smem_u32(smem + SM_B);

    if (tid < 128) { srmax[tid] = 0u; scnt[tid] = 0; }   // funmap(0)=NaN, ignored by fmaxf

    // load A tile (128 rows x 256 dims) = 4096 uint4
    {
        const uint4* Ag = reinterpret_cast<const uint4*>(zb + (size_t)row0 * DIM);
#pragma unroll
        for (int i = 0; i < 8; i++) {
            int u = tid + i * NTHR;
            int r = u >> 5, ch = u & 31;
            reinterpret_cast<uint4*>(As + r * PITCHA + ch * 8)[0] = Ag[u];
        }
    }

    // prefetch stages 0,1  (each stage: 128 codes x 128 dims = 2048 x 16B)
#pragma unroll
    for (int hi = 0; hi < 2; hi++) {
        const __nv_bfloat16* src = cb + (size_t)((hi >> 1) * 128) * DIM + (hi & 1) * 128;
        uint32_t dbase = sbB + (uint32_t)((hi % 3) * BBUF);
#pragma unroll
        for (int i = 0; i < 4; i++) {
            int u = tid + i * NTHR, code = u >> 4, seg = u & 15;
            cpasync16(dbase + (uint32_t)((code * PITCHB + seg * 8) * 2),
                      src + (size_t)code * DIM + seg * 8);
        }
        asm volatile("cp.async.commit_group;");
    }

    const int wid = tid >> 5, lane = tid & 31;
    const int wm = wid & 3, wn = wid >> 2;         // 4 x 4 warp grid
    const int gq = lane >> 2, t4 = lane & 3;

    const uint32_t aBase = sbA + (uint32_t)(((wm*32 + (lane & 15)) * PITCHA + (lane >> 4) * 8) * 2);
    const uint32_t bOff  = (uint32_t)(((wn*32 + (lane & 15)) * PITCHB + (lane >> 4) * 8) * 2);

    const int rl0 = wm*32 + gq;                 // local rows: rl0, rl0+8 (mt=0); +16, +24 (mt=1)
    __syncthreads();   // A + smem init visible

    for (int c = 0; c < 64; c++) {
        float acc[2][4][4];
#pragma unroll
        for (int mt = 0; mt < 2; mt++)
#pragma unroll
            for (int nt = 0; nt < 4; nt++)
#pragma unroll
                for (int q = 0; q < 4; q++) acc[mt][nt][q] = 0.0f;

#pragma unroll
        for (int kh = 0; kh < 2; kh++) {
            int hi = c*2 + kh;
            if (hi == 127) asm volatile("cp.async.wait_group 0;");
            else           asm volatile("cp.async.wait_group 1;");
            __syncthreads();
            if (hi + 2 < 128) {
                int h2 = hi + 2;
                const __nv_bfloat16* src = cb + (size_t)((h2 >> 1) * 128) * DIM + (h2 & 1) * 128;
                uint32_t dbase = sbB + (uint32_t)((h2 % 3) * BBUF);
#pragma unroll
                for (int i = 0; i < 4; i++) {
                    int u = tid + i * NTHR, code = u >> 4, seg = u & 15;
                    cpasync16(dbase + (uint32_t)((code * PITCHB + seg * 8) * 2),
                              src + (size_t)code * DIM + seg * 8);
                }
                asm volatile("cp.async.commit_group;");
            }

            uint32_t bBase = sbB + (uint32_t)((hi % 3) * BBUF) + bOff;
#pragma unroll
            for (int k8 = 0; k8 < 8; k8++) {
                uint32_t a[2][4], b[2][4];
#pragma unroll
                for (int mt = 0; mt < 2; mt++)
                    ldsm4(a[mt][0], a[mt][1], a[mt][2], a[mt][3],
                          aBase + (uint32_t)(((mt*16)*PITCHA + kh*128 + k8*16) * 2));
#pragma unroll
                for (int ng = 0; ng < 2; ng++)
                    ldsm4(b[ng][0], b[ng][1], b[ng][2], b[ng][3],
                          bBase + (uint32_t)(((ng*16)*PITCHB + k8*16) * 2));
#pragma unroll
                for (int mt = 0; mt < 2; mt++)
#pragma unroll
                    for (int ng = 0; ng < 2; ng++) {
                        mma16816(acc[mt][2*ng+0], a[mt][0], a[mt][1], a[mt][2], a[mt][3], b[ng][0], b[ng][2]);
                        mma16816(acc[mt][2*ng+1], a[mt][0], a[mt][1], a[mt][2], a[mt][3], b[ng][1], b[ng][3]);
                    }
            }
        }

        // ---- sync-free score-space epilogue -------------------------------
        // score = dot - 0.5*cnorm (maximize). Threshold = max(own quad max,
        // stale shared max) - HM: own-max covers the true argmin (sound);
        // stale shared is only looser (superset-safe). No __syncthreads.
#pragma unroll
        for (int mt = 0; mt < 2; mt++) {
            float sc[4][4];
            float mx_lo = -3.4e38f, mx_hi = -3.4e38f;
#pragma unroll
            for (int nt = 0; nt < 4; nt++) {
                int col = c*128 + wn*32 + nt*8 + t4*2;
                float2 cn = *reinterpret_cast<const float2*>(cnorm + col);
                sc[nt][0] = __fmaf_rn(cn.x, -0.5f, acc[mt][nt][0]);
                sc[nt][1] = __fmaf_rn(cn.y, -0.5f, acc[mt][nt][1]);
                sc[nt][2] = __fmaf_rn(cn.x, -0.5f, acc[mt][nt][2]);
                sc[nt][3] = __fmaf_rn(cn.y, -0.5f, acc[mt][nt][3]);
                mx_lo = fmaxf(mx_lo, fmaxf(sc[nt][0], sc[nt][1]));
                mx_hi = fmaxf(mx_hi, fmaxf(sc[nt][2], sc[nt][3]));
            }
#pragma unroll
            for (int o = 1; o < 4; o <<= 1) {
                mx_lo = fmaxf(mx_lo, __shfl_xor_sync(0xffffffffu, mx_lo, o));
                mx_hi = fmaxf(mx_hi, __shfl_xor_sync(0xffffffffu, mx_hi, o));
            }
            int rlo = rl0 + mt*16, rhi = rlo + 8;
            if (t4 == 0) {
                atomicMax(&srmax[rlo], fmap(mx_lo));
                atomicMax(&srmax[rhi], fmap(mx_hi));
            }
            float Tlo = fmaxf(mx_lo, funmap(srmax[rlo])) - HM;
            float Thi = fmaxf(mx_hi, funmap(srmax[rhi])) - HM;
#pragma unroll
            for (int nt = 0; nt < 4; nt++) {
                int col = c*128 + wn*32 + nt*8 + t4*2;
#pragma unroll
                for (int q = 0; q < 4; q++) {
                    int r    = (q < 2) ? rlo : rhi;
                    float T  = (q < 2) ? Tlo : Thi;
                    if (sc[nt][q] >= T) {
                        int pos = atomicAdd(&scnt[r], 1);
                        if (pos < CAP) scand[r*CAP + pos] = col + (q & 1);
                    }
                }
            }
        }
    }

    __syncthreads();   // candidates final

    // ---- fused exact refinement + scatter: warp `wid` owns local rows wid*8..+7
    for (int rr = 0; rr < 8; rr++) {
        int rl = wid * 8 + rr;
        int w  = row0 + rl;
        const float* zr = zf + (size_t)w * DIM;
        float szr = sumz[w];
        float bv = 3.4e38f; int bi = NC;
        int n = scnt[rl];
        if (n <= CAP) {
            for (int i = lane; i < n; i += 32) {
                int cc = scand[rl*CAP + i];
                const float* cr = cbw + (size_t)cc * DIM;
                float acc2 = 0.0f;
                for (int k2 = 0; k2 < DIM; k2++) acc2 = __fmaf_rn(zr[k2], cr[k2], acc2);
                float de = __fadd_rn(__fadd_rn(szr, -2.0f * acc2), cnorm[cc]);
                if (de < bv || (de == bv && cc < bi)) { bv = de; bi = cc; }
            }
        } else {
            for (int cc = lane; cc < NC; cc += 32) {
                const float* cr = cbw + (size_t)cc * DIM;
                float acc2 = 0.0f;
                for (int k2 = 0; k2 < DIM; k2++) acc2 = __fmaf_rn(zr[k2], cr[k2], acc2);
                float de = __fadd_rn(__fadd_rn(szr, -2.0f * acc2), cnorm[cc]);
                if (de < bv || (de == bv && cc < bi)) { bv = de; bi = cc; }
            }
        }
#pragma unroll
        for (int o = 16; o > 0; o >>= 1) {
            float ov = __shfl_xor_sync(0xffffffffu, bv, o);
            int   oi = __shfl_xor_sync(0xffffffffu, bi, o);
            if (ov < bv || (ov == bv && oi < bi)) { bv = ov; bi = oi; }
        }
        // all lanes hold (bv, bi) now
        if (lane == 0) idxf_out[w] = (float)bi;

        const float* cr = cbw + (size_t)bi * DIM;
        float ls = 0.0f;
#pragma unroll
        for (int m = 0; m < 8; m++) {
            int d = lane + 32*m;
            float zv = zr[d], cv = cr[d];
            atomicAdd(&wsum[bi * DIM + d], zv);
            float diff = __fadd_rn(zv, -cv);
            ls = __fadd_rn(ls, __fmul_rn(diff, diff));
            float st = __fadd_rn(cv, -zv);
            zq_out[(size_t)w * DIM + d] = __fadd_rn(zv, st);
        }
#pragma unroll
        for (int o = 16; o > 0; o >>= 1) ls = __fadd_rn(ls, __shfl_down_sync(0xffffffffu, ls, o));
        if (lane == 0) { atomicAdd(&cnt[bi], 1.0f); atomicAdd(lossacc, ls); }
    }
}

// ---------------- EMA count + n ----------------------------------------------
__global__ void k_ema(const float* __restrict__ ema_count, const float* __restrict__ cntv,
                      float* __restrict__ out_count, float* __restrict__ n_acc) {
    int c = blockIdx.x * blockDim.x + threadIdx.x;
    float nec = 0.0f;
    if (c < NC) {
        nec = __fadd_rn(__fmul_rn(0.99f, ema_count[c]), __fmul_rn(0.01f, cntv[c]));
        out_count[c] = nec;
    }
    __shared__ float red[256];
    red[threadIdx.x] = nec;
    __syncthreads();
    for (int s = 128; s > 0; s >>= 1) {
        if (threadIdx.x < s) red[threadIdx.x] = __fadd_rn(red[threadIdx.x], red[threadIdx.x + s]);
        __syncthreads();
    }
    if (threadIdx.x == 0) atomicAdd(n_acc, red[0]);
}

// ---------------- new codebook + new ema weight -------------------------------
__global__ void k_codebook(const float* __restrict__ ema_weight, const float* __restrict__ wsum,
                           const float* __restrict__ out_count, const float* __restrict__ n_acc,
                           float* __restrict__ out_cb, float* __restrict__ out_ew) {
    size_t i = (size_t)blockIdx.x * 256 + threadIdx.x;
    if (i >= (size_t)NC * DIM) return;
    int c = (int)(i >> 8);
    float new_ew = __fadd_rn(__fmul_rn(0.99f, ema_weight[i]), __fmul_rn(0.01f, wsum[i]));
    out_ew[i] = new_ew;
    float n  = *n_acc;
    float a  = __fadd_rn(out_count[c], 1e-5f);
    float b  = __fadd_rn(n, 0.08192f);
    float cs = __fmul_rn(__fdiv_rn(a, b), n);
    out_cb[i] = __fdiv_rn(new_ew, cs);
}

__global__ void k_loss(const float* __restrict__ lossacc, float* __restrict__ out_loss) {
    float m = __fdiv_rn(*lossacc, 8388608.0f);
    *out_loss = __fmul_rn(0.25f, m);
}

// ---------------- launch ------------------------------------------------------
extern "C" void kernel_launch(void* const* d_in, const int* in_sizes, int n_in,
                              void* d_out, int out_size) {
    const float* z          = (const float*)d_in[0];
    const float* cbw        = (const float*)d_in[1];
    const float* ema_count  = (const float*)d_in[2];
    const float* ema_weight = (const float*)d_in[3];

    float* out      = (float*)d_out;
    float* out_zq   = out;
    float* out_idx  = out + 8388608;
    float* out_loss = out + 8421376;
    float* out_cb   = out + 8421377;
    float* out_cnt  = out + 10518529;
    float* out_ew   = out + 10526721;

    float *p_sumz, *p_cnorm, *p_count, *p_wsum, *p_loss, *p_n;
    __nv_bfloat16 *p_zb, *p_cb;
    cudaGetSymbolAddress((void**)&p_sumz,  g_sumz);
    cudaGetSymbolAddress((void**)&p_cnorm, g_cnorm);
    cudaGetSymbolAddress((void**)&p_count, g_count);
    cudaGetSymbolAddress((void**)&p_wsum,  g_wsum);
    cudaGetSymbolAddress((void**)&p_loss,  g_loss);
    cudaGetSymbolAddress((void**)&p_n,     g_n);
    cudaGetSymbolAddress((void**)&p_zb,    g_zb);
    cudaGetSymbolAddress((void**)&p_cb,    g_cb);

    cudaFuncSetAttribute(k_mma, cudaFuncAttributeMaxDynamicSharedMemorySize, SMEM_TOTAL);

    k_zero<<<2048, 256>>>();
    k_prep<<<4096, 256>>>(z,   p_zb, p_sumz,  NROWS);
    k_prep<<<1024, 256>>>(cbw, p_cb, p_cnorm, NC);
    k_mma<<<NROWS/128, NTHR, SMEM_TOTAL>>>(p_zb, p_cb, z, cbw, p_sumz, p_cnorm,
                                           out_idx, out_zq, p_wsum, p_count, p_loss);
    k_ema<<<32, 256>>>(ema_count, p_count, out_cnt, p_n);
    k_codebook<<<8192, 256>>>(ema_weight, p_wsum, out_cnt, p_n, out_cb, out_ew);
    k_loss<<<1, 1>>>(p_loss, out_loss);
}

// round 10
// speedup vs baseline: 1.0275x; 1.0275x over previous
#include <cuda_runtime.h>
#include <cuda_bf16.h>
#include <cstdint>

#define NROWS 32768
#define DIM   256
#define NC    8192
#define HM    1e-4f             // score-space margin (= 2e-4 in dist space)
#define CAP   24

#define RCTA  64                // rows per CTA
#define NTHR  256               // 8 warps
#define PITCHA 264              // bf16 elems/row for A smem (256 + pad)
#define PITCHB 136              // bf16 elems/row for B smem (128 + pad)
#define BBUF   34816            // 128*136*2 bytes per B stage
// smem byte offsets
#define SM_A    0                                  // 64*264*2 = 33792
#define SM_B    33792                              // 2 stages
#define SM_CAND (SM_B + 2*BBUF)                    // 103424; 64*24*4 = 6144
#define SM_RMAX (SM_CAND + RCTA*CAP*4)             // 109568
#define SM_CNT  (SM_RMAX + 256)                    // 109824
#define SMEM_TOTAL (SM_CNT + 256)                  // 110080  (x2 = 220160/SM)

// ---------------- scratch ----------------------------------------------------
__device__ float g_sumz[NROWS];
__device__ float g_cnorm[NC];
__device__ float g_count[NC];
__device__ float g_wsum[NC * DIM];
__device__ float g_loss;
__device__ float g_n;
__device__ __nv_bfloat16 g_zb[NROWS * DIM];
__device__ __nv_bfloat16 g_cb[NC * DIM];

// ---------------- helpers -----------------------------------------------------
__device__ __forceinline__ uint32_t smem_u32(const void* p) {
    uint32_t a;
    asm("{ .reg .u64 t; cvta.to.shared.u64 t, %1; cvt.u32.u64 %0, t; }" : "=r"(a) : "l"(p));
    return a;
}
__device__ __forceinline__ void ldsm4(uint32_t& r0, uint32_t& r1, uint32_t& r2, uint32_t& r3, uint32_t addr) {
    asm volatile("ldmatrix.sync.aligned.m8n8.x4.shared.b16 {%0,%1,%2,%3}, [%4];"
                 : "=r"(r0), "=r"(r1), "=r"(r2), "=r"(r3) : "r"(addr));
}
__device__ __forceinline__ void mma16816(float* c, uint32_t a0, uint32_t a1, uint32_t a2, uint32_t a3,
                                         uint32_t b0, uint32_t b1) {
    asm volatile("mma.sync.aligned.m16n8k16.row.col.f32.bf16.bf16.f32 "
                 "{%0,%1,%2,%3}, {%4,%5,%6,%7}, {%8,%9}, {%0,%1,%2,%3};"
                 : "+f"(c[0]), "+f"(c[1]), "+f"(c[2]), "+f"(c[3])
                 : "r"(a0), "r"(a1), "r"(a2), "r"(a3), "r"(b0), "r"(b1));
}
__device__ __forceinline__ void cpasync16(uint32_t dst, const void* src) {
    asm volatile("cp.async.cg.shared.global [%0], [%1], 16;" :: "r"(dst), "l"(src));
}
// order-preserving float<->uint map (unsigned compare == float compare)
__device__ __forceinline__ uint32_t fmap(float f) {
    uint32_t b = __float_as_uint(f);
    return b ^ (uint32_t)(((int32_t)b >> 31) | 0x80000000);
}
__device__ __forceinline__ float funmap(uint32_t u) {
    uint32_t b = u ^ ((u >> 31) ? 0x80000000u : 0xFFFFFFFFu);
    return __uint_as_float(b);
}

// ---------------- zero scratch ------------------------------------------------
__global__ void k_zero() {
    int i = blockIdx.x * blockDim.x + threadIdx.x;
    int stride = gridDim.x * blockDim.x;
    for (int j = i; j < NC * DIM; j += stride) g_wsum[j] = 0.0f;
    if (i < NC) g_count[i] = 0.0f;
    if (i == 0) { g_loss = 0.0f; g_n = 0.0f; }
}

// ---------------- prep: row norms + bf16 round --------------------------------
__global__ void k_prep(const float* __restrict__ x, __nv_bfloat16* __restrict__ ob,
                       float* __restrict__ norm, int rows) {
    int w = (blockIdx.x * blockDim.x + threadIdx.x) >> 5;
    int lane = threadIdx.x & 31;
    if (w >= rows) return;
    const float* row = x + (size_t)w * DIM;
    float s = 0.0f;
#pragma unroll
    for (int m = 0; m < 8; m++) { float v = row[lane + 32*m]; s = __fadd_rn(s, __fmul_rn(v, v)); }
#pragma unroll
    for (int o = 16; o > 0; o >>= 1) s = __fadd_rn(s, __shfl_down_sync(0xffffffffu, s, o));
    if (lane == 0) norm[w] = s;

    __align__(16) __nv_bfloat16 b0[8];
#pragma unroll
    for (int q = 0; q < 8; q++) b0[q] = __float2bfloat16_rn(row[lane*8 + q]);
    *reinterpret_cast<uint4*>(ob + (size_t)w*DIM + lane*8) = *reinterpret_cast<uint4*>(b0);
}

// ---------------- fused: HMMA GEMM + candidates + exact argmin + scatter -------
// grid = 512 CTAs (64 rows each); loops 64 chunks of 128 codes (128 K-halves).
__global__ void __launch_bounds__(NTHR, 2) k_mma(
    const __nv_bfloat16* __restrict__ zb, const __nv_bfloat16* __restrict__ cb,
    const float* __restrict__ zf, const float* __restrict__ cbw,
    const float* __restrict__ sumz, const float* __restrict__ cnorm,
    float* __restrict__ idxf_out, float* __restrict__ zq_out,
    float* __restrict__ wsum, float* __restrict__ cnt, float* __restrict__ lossacc)
{
    extern __shared__ char smem[];
    __nv_bfloat16* As = reinterpret_cast<__nv_bfloat16*>(smem + SM_A);
    int*       scand = reinterpret_cast<int*>(smem + SM_CAND);
    uint32_t*  srmax = reinterpret_cast<uint32_t*>(smem + SM_RMAX);
    int*       scnt  = reinterpret_cast<int*>(smem + SM_CNT);

    const int tid = threadIdx.x;
    const int row0 = blockIdx.x * RCTA;
    const uint32_t sbA = smem_u32(smem + SM_A);
    const uint32_t sbB = smem_u32(smem + SM_B);

    if (tid < RCTA) { srmax[tid] = 0u; scnt[tid] = 0; }   // funmap(0)=NaN, ignored by fmaxf

    // load A tile (64 rows x 256 dims) = 2048 uint4
    {
        const uint4* Ag = reinterpret_cast<const uint4*>(zb + (size_t)row0 * DIM);
#pragma unroll
        for (int i = 0; i < 8; i++) {
            int u = tid + i * NTHR;
            int r = u >> 5, ch = u & 31;
            reinterpret_cast<uint4*>(As + r * PITCHA + ch * 8)[0] = Ag[u];
        }
    }

    // prefetch half-stage 0 (128 codes x 128 dims = 2048 x 16B)
    {
        const __nv_bfloat16* src = cb;            // chunk 0, kh 0
#pragma unroll
        for (int i = 0; i < 8; i++) {
            int u = tid + i * NTHR, code = u >> 4, seg = u & 15;
            cpasync16(sbB + (uint32_t)((code * PITCHB + seg * 8) * 2),
                      src + (size_t)code * DIM + seg * 8);
        }
        asm volatile("cp.async.commit_group;");
    }

    const int wid = tid >> 5, lane = tid & 31;
    const int wm = wid & 1, wn = wid >> 1;         // 2 x 4 warp grid
    const int gq = lane >> 2, t4 = lane & 3;

    const uint32_t aBase = sbA + (uint32_t)(((wm*32 + (lane & 15)) * PITCHA + (lane >> 4) * 8) * 2);
    const uint32_t bOff  = (uint32_t)(((wn*32 + (lane & 15)) * PITCHB + (lane >> 4) * 8) * 2);

    const int rl0 = wm*32 + gq;                 // local rows: rl0, +8 (mt=0); +16, +24 (mt=1)

    float acc[2][4][4];

    for (int hi = 0; hi < 128; hi++) {
        const int c = hi >> 1, kh = hi & 1;
        if (kh == 0) {
#pragma unroll
            for (int mt = 0; mt < 2; mt++)
#pragma unroll
                for (int nt = 0; nt < 4; nt++)
#pragma unroll
                    for (int q = 0; q < 4; q++) acc[mt][nt][q] = 0.0f;
        }

        asm volatile("cp.async.wait_group 0;");
        __syncthreads();                         // stage hi%2 visible; stage (hi+1)%2 free

        if (hi + 1 < 128) {                      // prefetch next half-stage (overlaps compute)
            int h2 = hi + 1;
            const __nv_bfloat16* src = cb + (size_t)((h2 >> 1) * 128) * DIM + (h2 & 1) * 128;
            uint32_t dbase = sbB + (uint32_t)((h2 & 1 ? (hi & 1 ? 0 : 1) : (hi & 1 ? 1 : 0)) * 0); // placeholder
            dbase = sbB + (uint32_t)(((h2 & 1) ^ ((h2 >> 1) & 1) ^ (h2 & 1)) * 0);                 // placeholder
            dbase = sbB + (uint32_t)((h2 & 1) + ((h2 >> 1) & 0)) * 0;                               // placeholder
            dbase = sbB + (uint32_t)((h2 % 2) * 0);                                                 // placeholder
            dbase = sbB + (uint32_t)((h2 & 1) ? ((hi & 1) ? BBUF : BBUF) : 0);                      // placeholder
            dbase = sbB + (uint32_t)((h2 & 1) * BBUF);   // stage parity = half-index parity... 
            dbase = sbB + (uint32_t)((h2 % 2) * BBUF);
            // NOTE: stage index is h2 % 2 (half-stages alternate buffers)
#pragma unroll
            for (int i = 0; i < 8; i++) {
                int u = tid + i * NTHR, code = u >> 4, seg = u & 15;
                cpasync16(dbase + (uint32_t)((code * PITCHB + seg * 8) * 2),
                          src + (size_t)code * DIM + seg * 8);
            }
            asm volatile("cp.async.commit_group;");
        }

        uint32_t bBase = sbB + (uint32_t)((hi & 1) * BBUF) + bOff;
#pragma unroll
        for (int k8 = 0; k8 < 8; k8++) {
            uint32_t a[2][4], b[2][4];
#pragma unroll
            for (int mt = 0; mt < 2; mt++)
                ldsm4(a[mt][0], a[mt][1], a[mt][2], a[mt][3],
                      aBase + (uint32_t)(((mt*16)*PITCHA + kh*128 + k8*16) * 2));
#pragma unroll
            for (int ng = 0; ng < 2; ng++)
                ldsm4(b[ng][0], b[ng][1], b[ng][2], b[ng][3],
                      bBase + (uint32_t)(((ng*16)*PITCHB + k8*16) * 2));
#pragma unroll
            for (int mt = 0; mt < 2; mt++)
#pragma unroll
                for (int ng = 0; ng < 2; ng++) {
                    mma16816(acc[mt][2*ng+0], a[mt][0], a[mt][1], a[mt][2], a[mt][3], b[ng][0], b[ng][2]);
                    mma16816(acc[mt][2*ng+1], a[mt][0], a[mt][1], a[mt][2], a[mt][3], b[ng][1], b[ng][3]);
                }
        }

        if (kh == 0) continue;

        // ---- sync-free score-space epilogue (after kh=1: full-K dots) ------
#pragma unroll
        for (int mt = 0; mt < 2; mt++) {
            float sc[4][4];
            float mx_lo = -3.4e38f, mx_hi = -3.4e38f;
#pragma unroll
            for (int nt = 0; nt < 4; nt++) {
                int col = c*128 + wn*32 + nt*8 + t4*2;
                float2 cn = *reinterpret_cast<const float2*>(cnorm + col);
                sc[nt][0] = __fmaf_rn(cn.x, -0.5f, acc[mt][nt][0]);
                sc[nt][1] = __fmaf_rn(cn.y, -0.5f, acc[mt][nt][1]);
                sc[nt][2] = __fmaf_rn(cn.x, -0.5f, acc[mt][nt][2]);
                sc[nt][3] = __fmaf_rn(cn.y, -0.5f, acc[mt][nt][3]);
                mx_lo = fmaxf(mx_lo, fmaxf(sc[nt][0], sc[nt][1]));
                mx_hi = fmaxf(mx_hi, fmaxf(sc[nt][2], sc[nt][3]));
            }
#pragma unroll
            for (int o = 1; o < 4; o <<= 1) {
                mx_lo = fmaxf(mx_lo, __shfl_xor_sync(0xffffffffu, mx_lo, o));
                mx_hi = fmaxf(mx_hi, __shfl_xor_sync(0xffffffffu, mx_hi, o));
            }
            int rlo = rl0 + mt*16, rhi = rlo + 8;
            if (t4 == 0) {
                atomicMax(&srmax[rlo], fmap(mx_lo));
                atomicMax(&srmax[rhi], fmap(mx_hi));
            }
            float Tlo = fmaxf(mx_lo, funmap(srmax[rlo])) - HM;
            float Thi = fmaxf(mx_hi, funmap(srmax[rhi])) - HM;
#pragma unroll
            for (int nt = 0; nt < 4; nt++) {
                int col = c*128 + wn*32 + nt*8 + t4*2;
#pragma unroll
                for (int q = 0; q < 4; q++) {
                    int r    = (q < 2) ? rlo : rhi;
                    float T  = (q < 2) ? Tlo : Thi;
                    if (sc[nt][q] >= T) {
                        int pos = atomicAdd(&scnt[r], 1);
                        if (pos < CAP) scand[r*CAP + pos] = col + (q & 1);
                    }
                }
            }
        }
    }

    __syncthreads();   // candidates final

    // ---- fused exact refinement + scatter: warp `wid` owns local rows wid*8..+7
    for (int rr = 0; rr < 8; rr++) {
        int rl = wid * 8 + rr;
        int w  = row0 + rl;
        const float* zr = zf + (size_t)w * DIM;
        float szr = sumz[w];
        float bv = 3.4e38f; int bi = NC;
        int n = scnt[rl];
        if (n <= CAP) {
            for (int i = lane; i < n; i += 32) {
                int cc = scand[rl*CAP + i];
                const float* cr = cbw + (size_t)cc * DIM;
                float acc2 = 0.0f;
                for (int k2 = 0; k2 < DIM; k2++) acc2 = __fmaf_rn(zr[k2], cr[k2], acc2);
                float de = __fadd_rn(__fadd_rn(szr, -2.0f * acc2), cnorm[cc]);
                if (de < bv || (de == bv && cc < bi)) { bv = de; bi = cc; }
            }
        } else {
            for (int cc = lane; cc < NC; cc += 32) {
                const float* cr = cbw + (size_t)cc * DIM;
                float acc2 = 0.0f;
                for (int k2 = 0; k2 < DIM; k2++) acc2 = __fmaf_rn(zr[k2], cr[k2], acc2);
                float de = __fadd_rn(__fadd_rn(szr, -2.0f * acc2), cnorm[cc]);
                if (de < bv || (de == bv && cc < bi)) { bv = de; bi = cc; }
            }
        }
#pragma unroll
        for (int o = 16; o > 0; o >>= 1) {
            float ov = __shfl_xor_sync(0xffffffffu, bv, o);
            int   oi = __shfl_xor_sync(0xffffffffu, bi, o);
            if (ov < bv || (ov == bv && oi < bi)) { bv = ov; bi = oi; }
        }
        // all lanes hold (bv, bi) now
        if (lane == 0) idxf_out[w] = (float)bi;

        const float* cr = cbw + (size_t)bi * DIM;
        float ls = 0.0f;
#pragma unroll
        for (int m = 0; m < 8; m++) {
            int d = lane + 32*m;
            float zv = zr[d], cv = cr[d];
            atomicAdd(&wsum[bi * DIM + d], zv);
            float diff = __fadd_rn(zv, -cv);
            ls = __fadd_rn(ls, __fmul_rn(diff, diff));
            float st = __fadd_rn(cv, -zv);
            zq_out[(size_t)w * DIM + d] = __fadd_rn(zv, st);
        }
#pragma unroll
        for (int o = 16; o > 0; o >>= 1) ls = __fadd_rn(ls, __shfl_down_sync(0xffffffffu, ls, o));
        if (lane == 0) { atomicAdd(&cnt[bi], 1.0f); atomicAdd(lossacc, ls); }
    }
}

// ---------------- EMA count + n ----------------------------------------------
__global__ void k_ema(const float* __restrict__ ema_count, const float* __restrict__ cntv,
                      float* __restrict__ out_count, float* __restrict__ n_acc) {
    int c = blockIdx.x * blockDim.x + threadIdx.x;
    float nec = 0.0f;
    if (c < NC) {
        nec = __fadd_rn(__fmul_rn(0.99f, ema_count[c]), __fmul_rn(0.01f, cntv[c]));
        out_count[c] = nec;
    }
    __shared__ float red[256];
    red[threadIdx.x] = nec;
    __syncthreads();
    for (int s = 128; s > 0; s >>= 1) {
        if (threadIdx.x < s) red[threadIdx.x] = __fadd_rn(red[threadIdx.x], red[threadIdx.x + s]);
        __syncthreads();
    }
    if (threadIdx.x == 0) atomicAdd(n_acc, red[0]);
}

// ---------------- new codebook + new ema weight -------------------------------
__global__ void k_codebook(const float* __restrict__ ema_weight, const float* __restrict__ wsum,
                           const float* __restrict__ out_count, const float* __restrict__ n_acc,
                           float* __restrict__ out_cb, float* __restrict__ out_ew) {
    size_t i = (size_t)blockIdx.x * 256 + threadIdx.x;
    if (i >= (size_t)NC * DIM) return;
    int c = (int)(i >> 8);
    float new_ew = __fadd_rn(__fmul_rn(0.99f, ema_weight[i]), __fmul_rn(0.01f, wsum[i]));
    out_ew[i] = new_ew;
    float n  = *n_acc;
    float a  = __fadd_rn(out_count[c], 1e-5f);
    float b  = __fadd_rn(n, 0.08192f);
    float cs = __fmul_rn(__fdiv_rn(a, b), n);
    out_cb[i] = __fdiv_rn(new_ew, cs);
}

__global__ void k_loss(const float* __restrict__ lossacc, float* __restrict__ out_loss) {
    float m = __fdiv_rn(*lossacc, 8388608.0f);
    *out_loss = __fmul_rn(0.25f, m);
}

// ---------------- launch ------------------------------------------------------
extern "C" void kernel_launch(void* const* d_in, const int* in_sizes, int n_in,
                              void* d_out, int out_size) {
    const float* z          = (const float*)d_in[0];
    const float* cbw        = (const float*)d_in[1];
    const float* ema_count  = (const float*)d_in[2];
    const float* ema_weight = (const float*)d_in[3];

    float* out      = (float*)d_out;
    float* out_zq   = out;
    float* out_idx  = out + 8388608;
    float* out_loss = out + 8421376;
    float* out_cb   = out + 8421377;
    float* out_cnt  = out + 10518529;
    float* out_ew   = out + 10526721;

    float *p_sumz, *p_cnorm, *p_count, *p_wsum, *p_loss, *p_n;
    __nv_bfloat16 *p_zb, *p_cb;
    cudaGetSymbolAddress((void**)&p_sumz,  g_sumz);
    cudaGetSymbolAddress((void**)&p_cnorm, g_cnorm);
    cudaGetSymbolAddress((void**)&p_count, g_count);
    cudaGetSymbolAddress((void**)&p_wsum,  g_wsum);
    cudaGetSymbolAddress((void**)&p_loss,  g_loss);
    cudaGetSymbolAddress((void**)&p_n,     g_n);
    cudaGetSymbolAddress((void**)&p_zb,    g_zb);
    cudaGetSymbolAddress((void**)&p_cb,    g_cb);

    cudaFuncSetAttribute(k_mma, cudaFuncAttributeMaxDynamicSharedMemorySize, SMEM_TOTAL);

    k_zero<<<2048, 256>>>();
    k_prep<<<4096, 256>>>(z,   p_zb, p_sumz,  NROWS);
    k_prep<<<1024, 256>>>(cbw, p_cb, p_cnorm, NC);
    k_mma<<<NROWS/RCTA, NTHR, SMEM_TOTAL>>>(p_zb, p_cb, z, cbw, p_sumz, p_cnorm,
                                            out_idx, out_zq, p_wsum, p_count, p_loss);
    k_ema<<<32, 256>>>(ema_count, p_count, out_cnt, p_n);
    k_codebook<<<8192, 256>>>(ema_weight, p_wsum, out_cnt, p_n, out_cb, out_ew);
    k_loss<<<1, 1>>>(p_loss, out_loss);
}